// round 1
// baseline (speedup 1.0000x reference)
#include <cuda_runtime.h>
#include <math.h>

#define N     1024
#define NN    (N*N)
#define NB    32
#define NSTEP (N/NB)
#define BATCH 16

// ---------------- device scratch (no allocations allowed) ----------------
__device__ float g_lu[(size_t)BATCH * NN];   // 64 MB destructible LU workspace
__device__ float g_comb[(size_t)3 * NN];     // combined right-hand matrices C0,C1,C2
__device__ float g_logdet[BATCH];
__device__ int   g_piv[BATCH * NB];          // pivots of current panel step (reused)

struct Hdr {
    int   active;
    int   idx[8];
    float weff[10];
    float beff;
};
__device__ Hdr g_hdr;

// ---------------- stage A: copy x -> LU workspace, zero logdets ----------------
__global__ void copy_kernel(const float* __restrict__ x) {
    size_t i = (size_t)blockIdx.x * blockDim.x + threadIdx.x;
    const float4* src = (const float4*)x;
    float4* dst = (float4*)g_lu;
    if (i < (size_t)BATCH * NN / 4) dst[i] = src[i];
    if (i < BATCH) g_logdet[i] = 0.0f;
}

// ---------------- stage B1: panel factorization (partial pivoting) ----------------
// One CTA per matrix. Panel (R x NB) lives in shared memory.
__global__ void __launch_bounds__(1024) lu_panel(int k) {
    int m = blockIdx.x;
    float* A = g_lu + (size_t)m * NN;
    int kb = k * NB;
    int R  = N - kb;
    extern __shared__ float s[];
    const int LD = NB + 1;
    int tid = threadIdx.x;

    for (int i = tid; i < R * NB; i += 1024) {
        int r = i / NB, j = i % NB;
        s[r * LD + j] = A[(size_t)(kb + r) * N + kb + j];
    }
    __shared__ float rv[32];
    __shared__ int   ri[32];
    __shared__ int   spiv;
    __shared__ float sld;
    if (tid == 0) sld = 0.0f;
    __syncthreads();

    for (int j = 0; j < NB; j++) {
        // ---- pivot search over column j, rows j..R-1 ----
        float best = -1.0f;
        int   bi   = 0x7fffffff;
        for (int r = j + tid; r < R; r += 1024) {
            float v = fabsf(s[r * LD + j]);
            if (v > best) { best = v; bi = r; }
        }
        for (int o = 16; o > 0; o >>= 1) {
            float ov = __shfl_down_sync(0xffffffffu, best, o);
            int   oi = __shfl_down_sync(0xffffffffu, bi, o);
            if (ov > best || (ov == best && oi < bi)) { best = ov; bi = oi; }
        }
        if ((tid & 31) == 0) { rv[tid >> 5] = best; ri[tid >> 5] = bi; }
        __syncthreads();
        if (tid == 0) {
            float bv = rv[0]; int bb = ri[0];
            for (int w = 1; w < 32; w++)
                if (rv[w] > bv || (rv[w] == bv && ri[w] < bb)) { bv = rv[w]; bb = ri[w]; }
            spiv = bb;
            g_piv[m * NB + j] = kb + bb;          // global pivot row
            sld += logf(fmaxf(bv, 1e-45f));       // log|pivot|
        }
        __syncthreads();
        int pr = spiv;
        if (pr != j && tid < NB) {                 // swap full panel width
            float t = s[j * LD + tid];
            s[j * LD + tid] = s[pr * LD + tid];
            s[pr * LD + tid] = t;
        }
        __syncthreads();
        float inv = 1.0f / s[j * LD + j];
        for (int r = j + 1 + tid; r < R; r += 1024) {
            float lv = s[r * LD + j] * inv;
            s[r * LD + j] = lv;
            #pragma unroll
            for (int jj = 0; jj < NB; jj++)
                if (jj > j) s[r * LD + jj] -= lv * s[j * LD + jj];
        }
        __syncthreads();
    }

    for (int i = tid; i < R * NB; i += 1024) {
        int r = i / NB, j = i % NB;
        A[(size_t)(kb + r) * N + kb + j] = s[r * LD + j];
    }
    if (tid == 0) g_logdet[m] += sld;
}

// ---------------- stage B2: apply row swaps to trailing cols + TRSM (U12) ----------------
__global__ void __launch_bounds__(128) lu_trsm(int k) {
    int kb  = k * NB;
    int off = kb + NB;
    int W   = N - off;
    int m   = blockIdx.y;
    float* A = g_lu + (size_t)m * NN;

    __shared__ float L[NB][NB + 1];
    __shared__ int   piv[NB];
    int tid = threadIdx.x;
    for (int i = tid; i < NB * NB; i += 128) {
        int r = i / NB, j = i % NB;
        L[r][j] = A[(size_t)(kb + r) * N + kb + j];
    }
    if (tid < NB) piv[tid] = g_piv[m * NB + tid];
    __syncthreads();

    int c = blockIdx.x * 128 + tid;
    if (c >= W) return;
    int col = off + c;

    // sequential row swaps (order matters), column-local so no races
    #pragma unroll 1
    for (int j = 0; j < NB; j++) {
        int p = piv[j];
        if (p != kb + j) {
            float t = A[(size_t)(kb + j) * N + col];
            A[(size_t)(kb + j) * N + col] = A[(size_t)p * N + col];
            A[(size_t)p * N + col] = t;
        }
    }
    // unit-lower forward substitution
    float v[NB];
    #pragma unroll
    for (int i = 0; i < NB; i++) v[i] = A[(size_t)(kb + i) * N + col];
    #pragma unroll
    for (int j = 0; j < NB; j++) {
        #pragma unroll
        for (int i = j + 1; i < NB; i++) v[i] -= L[i][j] * v[j];
    }
    #pragma unroll
    for (int i = 0; i < NB; i++) A[(size_t)(kb + i) * N + col] = v[i];
}

// ---------------- stage B3: trailing update A22 -= L21 * U12 ----------------
__global__ void __launch_bounds__(256) lu_gemm(int k) {
    int kb  = k * NB;
    int off = kb + NB;
    int W   = N - off;
    int m   = blockIdx.z;
    float* A = g_lu + (size_t)m * NN;
    int r0 = blockIdx.y * 64, c0 = blockIdx.x * 64;

    __shared__ float sL[64][NB + 1];
    __shared__ float sU[NB][64];
    int tid = threadIdx.x;
    for (int i = tid; i < 64 * NB; i += 256) {
        int r = i / NB, j = i % NB;
        int row = r0 + r;
        sL[r][j] = (row < W) ? A[(size_t)(off + row) * N + kb + j] : 0.0f;
    }
    for (int i = tid; i < NB * 64; i += 256) {
        int j = i / 64, c = i % 64;
        int col = c0 + c;
        sU[j][c] = (col < W) ? A[(size_t)(kb + j) * N + off + col] : 0.0f;
    }
    __syncthreads();

    int tx = tid & 15, ty = tid >> 4;
    float acc[4][4] = {};
    #pragma unroll
    for (int j = 0; j < NB; j++) {
        float4 bv = *(const float4*)&sU[j][tx * 4];
        float b[4] = {bv.x, bv.y, bv.z, bv.w};
        float a[4];
        #pragma unroll
        for (int i = 0; i < 4; i++) a[i] = sL[ty * 4 + i][j];
        #pragma unroll
        for (int i = 0; i < 4; i++)
            #pragma unroll
            for (int l = 0; l < 4; l++) acc[i][l] += a[i] * b[l];
    }
    #pragma unroll
    for (int i = 0; i < 4; i++) {
        int row = r0 + ty * 4 + i;
        if (row >= W) continue;
        #pragma unroll
        for (int l = 0; l < 4; l++) {
            int col = c0 + tx * 4 + l;
            if (col < W) A[(size_t)(off + row) * N + off + col] -= acc[i][l];
        }
    }
}

// ---------------- stage C: scores, top-k, fused weights, bool output ----------------
__global__ void head_kernel(const unsigned char* __restrict__ flags,
                            const float* __restrict__ w1, const float* __restrict__ b1,
                            const float* __restrict__ w2, const float* __restrict__ b2,
                            float* __restrict__ out, int out_size) {
    if (blockIdx.x != 0 || threadIdx.x != 0) return;

    // decode bool flags (heuristic: if any byte at pos%4!=0 is set -> 1-byte bools)
    int f[16];
    bool any_off4 = false;
    for (int i = 0; i < 16; i++)
        if ((i & 3) && flags[i]) any_off4 = true;
    if (any_off4) {
        for (int i = 0; i < 16; i++) f[i] = flags[i] ? 1 : 0;
    } else {
        const int* fi = (const int*)flags;
        for (int i = 0; i < 16; i++) f[i] = fi[i] ? 1 : 0;
    }

    int sum = 0;
    for (int i = 0; i < 16; i++) sum += f[i];
    int active = (sum >= 4) ? 1 : 0;

    float neg_inf = __int_as_float(0xff800000);
    float sc[16];
    for (int i = 0; i < 16; i++) sc[i] = f[i] ? g_logdet[i] : neg_inf;

    int used[16] = {};
    for (int t = 0; t < 8; t++) {
        int best = -1;
        float bv = neg_inf;
        for (int i = 0; i < 16; i++) {
            if (used[i]) continue;
            if (best < 0 || sc[i] > bv) { best = i; bv = sc[i]; }
        }
        used[best] = 1;
        g_hdr.idx[t] = best;
    }

    for (int c = 0; c < 10; c++) {
        float a = 0.0f;
        for (int h = 0; h < 32; h++) a += w2[h] * w1[h * 10 + c];
        g_hdr.weff[c] = a;
    }
    float be = b2[0];
    for (int h = 0; h < 32; h++) be += w2[h] * b1[h];
    g_hdr.beff = be;
    g_hdr.active = active;

    // bool output (flattened after the main tensor)
    for (int i = NN; i < out_size; i++) out[i] = active ? 1.0f : 0.0f;
}

// ---------------- stage D1: combined right matrices ----------------
__global__ void combine_kernel(const float* __restrict__ x) {
    int i = blockIdx.x * blockDim.x + threadIdx.x;
    if (i >= NN / 4) return;
    const float4* T1 = (const float4*)(x + (size_t)g_hdr.idx[1] * NN);
    const float4* T2 = (const float4*)(x + (size_t)g_hdr.idx[2] * NN);
    const float4* T3 = (const float4*)(x + (size_t)g_hdr.idx[3] * NN);
    float w0 = g_hdr.weff[0], w1 = g_hdr.weff[1], w2 = g_hdr.weff[2];
    float w3 = g_hdr.weff[3], w4 = g_hdr.weff[4], w5 = g_hdr.weff[5];
    float4 a = T1[i], b = T2[i], c = T3[i];
    float4 r0, r1, r2;
    r0.x = w0*a.x + w1*b.x + w2*c.x;  r0.y = w0*a.y + w1*b.y + w2*c.y;
    r0.z = w0*a.z + w1*b.z + w2*c.z;  r0.w = w0*a.w + w1*b.w + w2*c.w;
    r1.x = w3*b.x + w4*c.x;  r1.y = w3*b.y + w4*c.y;
    r1.z = w3*b.z + w4*c.z;  r1.w = w3*b.w + w4*c.w;
    r2.x = w5*c.x;  r2.y = w5*c.y;  r2.z = w5*c.z;  r2.w = w5*c.w;
    ((float4*)g_comb)[i]            = r0;
    ((float4*)(g_comb + NN))[i]     = r1;
    ((float4*)(g_comb + 2*NN))[i]   = r2;
}

// ---------------- stage D2: fused 3-GEMM + preserve channels + bias ----------------
__global__ void __launch_bounds__(256) final_kernel(const float* __restrict__ x,
                                                    float* __restrict__ out, int out_size) {
    __shared__ float sA[3][64][NB];     // unpadded: 2-way conflict acceptable (48KB limit)
    __shared__ float sB[3][NB][64];
    int r0 = blockIdx.y * 64, c0 = blockIdx.x * 64;
    int tid = threadIdx.x, tx = tid & 15, ty = tid >> 4;

    if (!g_hdr.active) {
        #pragma unroll
        for (int i = 0; i < 4; i++) {
            int row = r0 + ty * 4 + i;
            #pragma unroll
            for (int l = 0; l < 4; l++) {
                int p = row * N + c0 + tx * 4 + l;
                if (p < out_size) out[p] = 0.0f;
            }
        }
        return;
    }

    const float* L[3] = { x + (size_t)g_hdr.idx[0] * NN,
                          x + (size_t)g_hdr.idx[1] * NN,
                          x + (size_t)g_hdr.idx[2] * NN };
    const float* C[3] = { g_comb, g_comb + NN, g_comb + 2 * NN };

    float acc[4][4] = {};
    for (int kc = 0; kc < N; kc += NB) {
        for (int i = tid; i < 3 * 64 * NB; i += 256) {
            int mm = i / (64 * NB);
            int rem = i % (64 * NB);
            int r = rem / NB, j = rem % NB;
            sA[mm][r][j] = L[mm][(size_t)(r0 + r) * N + kc + j];
        }
        for (int i = tid; i < 3 * NB * 64; i += 256) {
            int mm = i / (NB * 64);
            int rem = i % (NB * 64);
            int j = rem / 64, c = rem % 64;
            sB[mm][j][c] = C[mm][(size_t)(kc + j) * N + c0 + c];
        }
        __syncthreads();
        #pragma unroll
        for (int jj = 0; jj < NB; jj++) {
            float a0[4], a1[4], a2[4];
            #pragma unroll
            for (int i = 0; i < 4; i++) {
                a0[i] = sA[0][ty * 4 + i][jj];
                a1[i] = sA[1][ty * 4 + i][jj];
                a2[i] = sA[2][ty * 4 + i][jj];
            }
            float4 b0v = *(const float4*)&sB[0][jj][tx * 4];
            float4 b1v = *(const float4*)&sB[1][jj][tx * 4];
            float4 b2v = *(const float4*)&sB[2][jj][tx * 4];
            float b0[4] = {b0v.x, b0v.y, b0v.z, b0v.w};
            float b1a[4] = {b1v.x, b1v.y, b1v.z, b1v.w};
            float b2a[4] = {b2v.x, b2v.y, b2v.z, b2v.w};
            #pragma unroll
            for (int i = 0; i < 4; i++)
                #pragma unroll
                for (int l = 0; l < 4; l++)
                    acc[i][l] += a0[i] * b0[l] + a1[i] * b1a[l] + a2[i] * b2a[l];
        }
        __syncthreads();
    }

    const float* P0 = x + (size_t)g_hdr.idx[4] * NN;
    const float* P1 = x + (size_t)g_hdr.idx[5] * NN;
    const float* P2 = x + (size_t)g_hdr.idx[6] * NN;
    const float* P3 = x + (size_t)g_hdr.idx[7] * NN;
    float w6 = g_hdr.weff[6], w7 = g_hdr.weff[7], w8 = g_hdr.weff[8], w9 = g_hdr.weff[9];
    float be = g_hdr.beff;

    #pragma unroll
    for (int i = 0; i < 4; i++) {
        int row = r0 + ty * 4 + i;
        #pragma unroll
        for (int l = 0; l < 4; l++) {
            int col = c0 + tx * 4 + l;
            int p = row * N + col;
            float v = acc[i][l] + w6 * P0[p] + w7 * P1[p] + w8 * P2[p] + w9 * P3[p] + be;
            if (p < out_size) out[p] = v;
        }
    }
}

// ---------------- host launcher ----------------
extern "C" void kernel_launch(void* const* d_in, const int* in_sizes, int n_in,
                              void* d_out, int out_size) {
    const float*         x     = (const float*)d_in[0];
    const unsigned char* flags = (const unsigned char*)d_in[1];
    const float*         w1    = (const float*)d_in[2];
    const float*         b1    = (const float*)d_in[3];
    const float*         w2    = (const float*)d_in[4];
    const float*         b2    = (const float*)d_in[5];
    float*               out   = (float*)d_out;

    cudaFuncSetAttribute(lu_panel, cudaFuncAttributeMaxDynamicSharedMemorySize,
                         N * (NB + 1) * (int)sizeof(float));

    copy_kernel<<<(BATCH * NN / 4 + 255) / 256, 256>>>(x);

    for (int k = 0; k < NSTEP; k++) {
        int kb = k * NB;
        int R  = N - kb;
        int W  = N - kb - NB;
        lu_panel<<<BATCH, 1024, R * (NB + 1) * (int)sizeof(float)>>>(k);
        if (W > 0) {
            dim3 tg((W + 127) / 128, BATCH);
            lu_trsm<<<tg, 128>>>(k);
            dim3 gg((W + 63) / 64, (W + 63) / 64, BATCH);
            lu_gemm<<<gg, 256>>>(k);
        }
    }

    head_kernel<<<1, 1>>>(flags, w1, b1, w2, b2, out, out_size);
    combine_kernel<<<(NN / 4 + 255) / 256, 256>>>(x);
    final_kernel<<<dim3(16, 16), 256>>>(x, out, out_size);
}

// round 3
// speedup vs baseline: 1.3397x; 1.3397x over previous
#include <cuda_runtime.h>
#include <math.h>

#define N     1024
#define NN    (N*N)
#define NB    32
#define NSTEP (N/NB)
#define BATCH 16

// ---------------- device scratch (no allocations allowed) ----------------
__device__ float g_lu[(size_t)BATCH * NN];   // 64 MB destructible LU workspace
__device__ float g_comb[(size_t)3 * NN];     // combined right-hand matrices C0,C1,C2
__device__ float g_logdet[BATCH];

struct Hdr {
    int   active;
    int   idx[8];
    float weff[10];
    float beff;
};
__device__ Hdr g_hdr;

// ---------------- stage A: copy x -> LU workspace, zero logdets ----------------
__global__ void copy_kernel(const float* __restrict__ x) {
    size_t i = (size_t)blockIdx.x * blockDim.x + threadIdx.x;
    const float4* src = (const float4*)x;
    float4* dst = (float4*)g_lu;
    if (i < (size_t)BATCH * NN / 4) dst[i] = src[i];
    if (i < BATCH) g_logdet[i] = 0.0f;
}

// ---------------- stage B1: panel factorization (partial pivoting) + trailing swaps ----
// One CTA per matrix. Panel (R x NB) in shared. After factorization, this CTA
// also applies the 32 row swaps to the trailing columns (column-per-thread,
// no syncs needed: swaps are column-local).
__global__ void __launch_bounds__(512) lu_panel(int k) {
    int m = blockIdx.x;
    float* A = g_lu + (size_t)m * NN;
    int kb  = k * NB;
    int R   = N - kb;
    int off = kb + NB;
    int W   = N - off;
    extern __shared__ float s[];
    const int LD = NB + 1;
    int tid = threadIdx.x;

    __shared__ float rv[16];
    __shared__ int   ri[16];
    __shared__ int   spiv[NB];
    __shared__ float sld;

    for (int i = tid; i < R * NB; i += 512) {
        int r = i / NB, j = i % NB;
        s[r * LD + j] = A[(size_t)(kb + r) * N + kb + j];
    }
    if (tid == 0) sld = 0.0f;
    __syncthreads();

    for (int j = 0; j < NB; j++) {
        // ---- pivot search over column j, rows j..R-1 ----
        float best = -1.0f;
        int   bi   = 0x7fffffff;
        for (int r = j + tid; r < R; r += 512) {
            float v = fabsf(s[r * LD + j]);
            if (v > best) { best = v; bi = r; }
        }
        #pragma unroll
        for (int o = 16; o > 0; o >>= 1) {
            float ov = __shfl_down_sync(0xffffffffu, best, o);
            int   oi = __shfl_down_sync(0xffffffffu, bi, o);
            if (ov > best || (ov == best && oi < bi)) { best = ov; bi = oi; }
        }
        if ((tid & 31) == 0) { rv[tid >> 5] = best; ri[tid >> 5] = bi; }
        __syncthreads();
        if (tid < 32) {
            float b2 = (tid < 16) ? rv[tid] : -2.0f;
            int   i2 = (tid < 16) ? ri[tid] : 0x7fffffff;
            #pragma unroll
            for (int o = 8; o > 0; o >>= 1) {
                float ov = __shfl_down_sync(0xffffffffu, b2, o);
                int   oi = __shfl_down_sync(0xffffffffu, i2, o);
                if (ov > b2 || (ov == b2 && oi < i2)) { b2 = ov; i2 = oi; }
            }
            if (tid == 0) {
                spiv[j] = i2;
                sld += logf(fmaxf(b2, 1e-45f));
            }
        }
        __syncthreads();
        int pr = spiv[j];
        if (pr != j && tid < NB) {
            float t = s[j * LD + tid];
            s[j * LD + tid] = s[pr * LD + tid];
            s[pr * LD + tid] = t;
        }
        __syncthreads();
        float inv = 1.0f / s[j * LD + j];
        for (int r = j + 1 + tid; r < R; r += 512) {
            float lv = s[r * LD + j] * inv;
            s[r * LD + j] = lv;
            #pragma unroll
            for (int jj = 0; jj < NB; jj++)
                if (jj > j) s[r * LD + jj] -= lv * s[j * LD + jj];
        }
        __syncthreads();
    }

    // write back factored panel (diag block + scaled L21)
    for (int i = tid; i < R * NB; i += 512) {
        int r = i / NB, j = i % NB;
        A[(size_t)(kb + r) * N + kb + j] = s[r * LD + j];
    }
    if (tid == 0) g_logdet[m] += sld;

    // ---- apply row swaps to trailing columns (column-local, no syncs) ----
    for (int c = tid; c < W; c += 512) {
        int col = off + c;
        #pragma unroll 1
        for (int j = 0; j < NB; j++) {
            int p = spiv[j];
            if (p != j) {
                float t = A[(size_t)(kb + j) * N + col];
                A[(size_t)(kb + j) * N + col] = A[(size_t)(kb + p) * N + col];
                A[(size_t)(kb + p) * N + col] = t;
            }
        }
    }
}

// ---------------- stage B2: fused local-TRSM + trailing update ----------------
// One CTA per 128x64 tile of the Schur complement. L21 is already factored
// in global (panel wrote it back scaled). Each CTA solves ONLY its own 32x64
// U12 strip locally (L11 forward substitution, redundant per row-tile) and
// updates its A22 tile. U12 is never written back (never needed again).
__global__ void __launch_bounds__(256) lu_update(int k) {
    int kb  = k * NB;
    int off = kb + NB;
    int W   = N - off;
    int m   = blockIdx.z;
    float* A = g_lu + (size_t)m * NN;
    int r0 = blockIdx.y * 128, c0 = blockIdx.x * 64;
    int tid = threadIdx.x;

    __shared__ float D[NB][NB + 1];     // factored diag block (L unit-lower + U)
    __shared__ float sL[128][NB + 1];   // L21 strip (this CTA's rows)
    __shared__ float sU[NB][68];        // U12 strip (this CTA's cols)

    for (int i = tid; i < NB * NB; i += 256) {
        int r = i / NB, c = i % NB;
        D[r][c] = A[(size_t)(kb + r) * N + kb + c];
    }
    for (int i = tid; i < 128 * NB; i += 256) {
        int r = i / NB, j = i % NB;
        int row = r0 + r;
        sL[r][j] = (row < W) ? A[(size_t)(off + row) * N + kb + j] : 0.0f;
    }
    for (int i = tid; i < NB * 64; i += 256) {
        int r = i / 64, c = i % 64;
        int col = c0 + c;
        sU[r][c] = (col < W) ? A[(size_t)(kb + r) * N + off + col] : 0.0f;
    }
    __syncthreads();

    // local TRSM: threads 0..63 each solve one U12 column (L11 unit-lower)
    if (tid < 64) {
        float v[NB];
        #pragma unroll
        for (int i = 0; i < NB; i++) v[i] = sU[i][tid];
        #pragma unroll 1
        for (int j = 0; j < NB; j++) {
            float vj = v[j];
            #pragma unroll
            for (int i = 0; i < NB; i++)
                if (i > j) v[i] -= D[i][j] * vj;
        }
        #pragma unroll
        for (int i = 0; i < NB; i++) sU[i][tid] = v[i];
    }
    __syncthreads();

    // trailing update: 128x64 tile, 8x4 per thread
    int tx = tid & 15, ty = tid >> 4;
    float acc[8][4] = {};
    #pragma unroll
    for (int j = 0; j < NB; j++) {
        float4 bv = *(const float4*)&sU[j][tx * 4];
        float b[4] = {bv.x, bv.y, bv.z, bv.w};
        float a[8];
        #pragma unroll
        for (int i = 0; i < 8; i++) a[i] = sL[ty * 8 + i][j];
        #pragma unroll
        for (int i = 0; i < 8; i++)
            #pragma unroll
            for (int l = 0; l < 4; l++) acc[i][l] += a[i] * b[l];
    }
    #pragma unroll
    for (int i = 0; i < 8; i++) {
        int row = r0 + ty * 8 + i;
        if (row >= W) continue;
        float* orow = A + (size_t)(off + row) * N + off;
        #pragma unroll
        for (int l = 0; l < 4; l++) {
            int col = c0 + tx * 4 + l;
            if (col < W) orow[col] -= acc[i][l];
        }
    }
}

// ---------------- stage C: scores, top-k, fused weights, bool output ----------------
__global__ void head_kernel(const unsigned char* __restrict__ flags,
                            const float* __restrict__ w1, const float* __restrict__ b1,
                            const float* __restrict__ w2, const float* __restrict__ b2,
                            float* __restrict__ out, int out_size) {
    if (blockIdx.x != 0 || threadIdx.x != 0) return;

    int f[16];
    bool any_off4 = false;
    for (int i = 0; i < 16; i++)
        if ((i & 3) && flags[i]) any_off4 = true;
    if (any_off4) {
        for (int i = 0; i < 16; i++) f[i] = flags[i] ? 1 : 0;
    } else {
        const int* fi = (const int*)flags;
        for (int i = 0; i < 16; i++) f[i] = fi[i] ? 1 : 0;
    }

    int sum = 0;
    for (int i = 0; i < 16; i++) sum += f[i];
    int active = (sum >= 4) ? 1 : 0;

    float neg_inf = __int_as_float(0xff800000);
    float sc[16];
    for (int i = 0; i < 16; i++) sc[i] = f[i] ? g_logdet[i] : neg_inf;

    int used[16] = {};
    for (int t = 0; t < 8; t++) {
        int best = -1;
        float bv = neg_inf;
        for (int i = 0; i < 16; i++) {
            if (used[i]) continue;
            if (best < 0 || sc[i] > bv) { best = i; bv = sc[i]; }
        }
        used[best] = 1;
        g_hdr.idx[t] = best;
    }

    for (int c = 0; c < 10; c++) {
        float a = 0.0f;
        for (int h = 0; h < 32; h++) a += w2[h] * w1[h * 10 + c];
        g_hdr.weff[c] = a;
    }
    float be = b2[0];
    for (int h = 0; h < 32; h++) be += w2[h] * b1[h];
    g_hdr.beff = be;
    g_hdr.active = active;

    for (int i = NN; i < out_size; i++) out[i] = active ? 1.0f : 0.0f;
}

// ---------------- stage D1: combined right matrices ----------------
__global__ void combine_kernel(const float* __restrict__ x) {
    int i = blockIdx.x * blockDim.x + threadIdx.x;
    if (i >= NN / 4) return;
    const float4* T1 = (const float4*)(x + (size_t)g_hdr.idx[1] * NN);
    const float4* T2 = (const float4*)(x + (size_t)g_hdr.idx[2] * NN);
    const float4* T3 = (const float4*)(x + (size_t)g_hdr.idx[3] * NN);
    float w0 = g_hdr.weff[0], w1 = g_hdr.weff[1], w2 = g_hdr.weff[2];
    float w3 = g_hdr.weff[3], w4 = g_hdr.weff[4], w5 = g_hdr.weff[5];
    float4 a = T1[i], b = T2[i], c = T3[i];
    float4 r0, r1, r2;
    r0.x = w0*a.x + w1*b.x + w2*c.x;  r0.y = w0*a.y + w1*b.y + w2*c.y;
    r0.z = w0*a.z + w1*b.z + w2*c.z;  r0.w = w0*a.w + w1*b.w + w2*c.w;
    r1.x = w3*b.x + w4*c.x;  r1.y = w3*b.y + w4*c.y;
    r1.z = w3*b.z + w4*c.z;  r1.w = w3*b.w + w4*c.w;
    r2.x = w5*c.x;  r2.y = w5*c.y;  r2.z = w5*c.z;  r2.w = w5*c.w;
    ((float4*)g_comb)[i]            = r0;
    ((float4*)(g_comb + NN))[i]     = r1;
    ((float4*)(g_comb + 2*NN))[i]   = r2;
}

// ---------------- stage D2: fused 3-GEMM + preserve channels + bias ----------------
#define SA(p,r,j) sA[((p) * 128 + (r)) * 33 + (j)]
#define SB(p,j,c) sB[((p) * NB + (j)) * 68 + (c)]
__global__ void __launch_bounds__(256) final_kernel(const float* __restrict__ x,
                                                    float* __restrict__ out, int out_size) {
    extern __shared__ float sm[];
    float* sA = sm;                         // 3 * 128 * 33
    float* sB = sm + 3 * 128 * 33;          // 3 * NB * 68

    int r0 = blockIdx.y * 128, c0 = blockIdx.x * 64;
    int tid = threadIdx.x, tx = tid & 15, ty = tid >> 4;

    if (!g_hdr.active) {
        #pragma unroll
        for (int i = 0; i < 8; i++) {
            int row = r0 + ty * 8 + i;
            #pragma unroll
            for (int l = 0; l < 4; l++) {
                int p = row * N + c0 + tx * 4 + l;
                if (p < out_size) out[p] = 0.0f;
            }
        }
        return;
    }

    const float* L[3] = { x + (size_t)g_hdr.idx[0] * NN,
                          x + (size_t)g_hdr.idx[1] * NN,
                          x + (size_t)g_hdr.idx[2] * NN };
    const float* C[3] = { g_comb, g_comb + NN, g_comb + 2 * NN };

    float acc[8][4] = {};
    for (int kc = 0; kc < N; kc += NB) {
        #pragma unroll
        for (int p = 0; p < 3; p++) {
            for (int i = tid; i < 128 * NB; i += 256) {
                int r = i / NB, j = i % NB;
                SA(p, r, j) = L[p][(size_t)(r0 + r) * N + kc + j];
            }
            for (int i = tid; i < NB * 64; i += 256) {
                int j = i / 64, c = i % 64;
                SB(p, j, c) = C[p][(size_t)(kc + j) * N + c0 + c];
            }
        }
        __syncthreads();
        #pragma unroll 4
        for (int jj = 0; jj < NB; jj++) {
            #pragma unroll
            for (int p = 0; p < 3; p++) {
                float4 bv = *(const float4*)&SB(p, jj, tx * 4);
                float b[4] = {bv.x, bv.y, bv.z, bv.w};
                float a[8];
                #pragma unroll
                for (int i = 0; i < 8; i++) a[i] = SA(p, ty * 8 + i, jj);
                #pragma unroll
                for (int i = 0; i < 8; i++)
                    #pragma unroll
                    for (int l = 0; l < 4; l++) acc[i][l] += a[i] * b[l];
            }
        }
        __syncthreads();
    }

    const float* P0 = x + (size_t)g_hdr.idx[4] * NN;
    const float* P1 = x + (size_t)g_hdr.idx[5] * NN;
    const float* P2 = x + (size_t)g_hdr.idx[6] * NN;
    const float* P3 = x + (size_t)g_hdr.idx[7] * NN;
    float w6 = g_hdr.weff[6], w7 = g_hdr.weff[7], w8 = g_hdr.weff[8], w9 = g_hdr.weff[9];
    float be = g_hdr.beff;

    #pragma unroll
    for (int i = 0; i < 8; i++) {
        int row = r0 + ty * 8 + i;
        #pragma unroll
        for (int l = 0; l < 4; l++) {
            int col = c0 + tx * 4 + l;
            int p = row * N + col;
            float v = acc[i][l] + w6 * P0[p] + w7 * P1[p] + w8 * P2[p] + w9 * P3[p] + be;
            if (p < out_size) out[p] = v;
        }
    }
}

// ---------------- host launcher ----------------
extern "C" void kernel_launch(void* const* d_in, const int* in_sizes, int n_in,
                              void* d_out, int out_size) {
    const float*         x     = (const float*)d_in[0];
    const unsigned char* flags = (const unsigned char*)d_in[1];
    const float*         w1    = (const float*)d_in[2];
    const float*         b1    = (const float*)d_in[3];
    const float*         w2    = (const float*)d_in[4];
    const float*         b2    = (const float*)d_in[5];
    float*               out   = (float*)d_out;

    int panel_smem = N * (NB + 1) * (int)sizeof(float);
    int fin_smem   = (3 * 128 * 33 + 3 * NB * 68) * (int)sizeof(float);
    cudaFuncSetAttribute(lu_panel, cudaFuncAttributeMaxDynamicSharedMemorySize, panel_smem);
    cudaFuncSetAttribute(final_kernel, cudaFuncAttributeMaxDynamicSharedMemorySize, fin_smem);

    copy_kernel<<<(BATCH * NN / 4 + 255) / 256, 256>>>(x);

    for (int k = 0; k < NSTEP; k++) {
        int kb = k * NB;
        int R  = N - kb;
        int W  = N - kb - NB;
        lu_panel<<<BATCH, 512, R * (NB + 1) * (int)sizeof(float)>>>(k);
        if (W > 0) {
            dim3 g((W + 63) / 64, (W + 127) / 128, BATCH);
            lu_update<<<g, 256>>>(k);
        }
    }

    head_kernel<<<1, 1>>>(flags, w1, b1, w2, b2, out, out_size);
    combine_kernel<<<(NN / 4 + 255) / 256, 256>>>(x);
    final_kernel<<<dim3(16, 8), 256, fin_smem>>>(x, out, out_size);
}